// round 4
// baseline (speedup 1.0000x reference)
#include <cuda_runtime.h>
#include <math.h>

// ESN: B=256, T=512, D=64, N=512, leak=0.5
// Output: [ X (B,T,N) fp32 ][ X_last (B,N) fp32 ]

#define BB 256
#define TT 512
#define DD 64
#define NN 512
#define LEAK 0.5f
#define NCTA 128
#define RK 68          // Xsd row stride (words); quad offsets stay < 64
#define NGRP 8
#define GRP_SZ 16

typedef unsigned long long ull;

__device__ unsigned g_cnt[NGRP * 32];   // 128B-spaced counters

__device__ __forceinline__ void fma2(ull &acc, ull a, ull b) {
    asm("fma.rn.f32x2 %0, %1, %2, %0;" : "+l"(acc) : "l"(a), "l"(b));
}
__device__ __forceinline__ float2 unpack2(ull v) {
    float2 r; asm("mov.b64 {%0, %1}, %2;" : "=f"(r.x), "=f"(r.y) : "l"(v)); return r;
}
__device__ __forceinline__ unsigned atom_add_rel(unsigned* p, unsigned v) {
    unsigned r;
    asm volatile("atom.add.release.gpu.global.u32 %0, [%1], %2;"
                 : "=r"(r) : "l"(p), "r"(v) : "memory");
    return r;
}
__device__ __forceinline__ unsigned ld_acq(const unsigned* p) {
    unsigned r;
    asm volatile("ld.acquire.gpu.global.u32 %0, [%1];" : "=r"(r) : "l"(p) : "memory");
    return r;
}

__global__ void init_kernel() {
    if (threadIdx.x < NGRP) g_cnt[threadIdx.x * 32] = 0u;
}

// ---------------------------------------------------------------------------
// Projection (unchanged): U = inputs@W_in + b_in; x0 = leak*tanh(U0) at t=0.
// ---------------------------------------------------------------------------
__global__ __launch_bounds__(128) void proj_kernel(
    const float* __restrict__ inp, const float* __restrict__ Win,
    const float* __restrict__ bin, float* __restrict__ X)
{
    __shared__ __align__(16) float As[DD][36];
    __shared__ __align__(16) float Wd[DD][64];

    const int tid = threadIdx.x;
    const int m0 = blockIdx.x * 32;
    const int n0 = blockIdx.y * 32;

    {
        int c = tid & 63, mi = tid >> 6;
        #pragma unroll
        for (int j = 0; j < 16; j++) {
            int m = j * 2 + mi;
            As[c][m] = inp[(m0 + m) * DD + c];
        }
    }
    {
        int n = tid & 31, kw = tid >> 5;
        #pragma unroll
        for (int j = 0; j < 16; j++) {
            int k = j * 4 + kw;
            float w = Win[k * NN + n0 + n];
            Wd[k][2 * n] = w; Wd[k][2 * n + 1] = w;
        }
    }
    __syncthreads();

    const int tx = tid & 7;
    const int ty = tid >> 3;
    ull acc0 = 0, acc1 = 0, acc2 = 0, acc3 = 0;

    #pragma unroll
    for (int k = 0; k < DD; k++) {
        ull a = *(const ull*)&As[k][2 * ty];
        const ulonglong2* bp = (const ulonglong2*)&Wd[k][8 * tx];
        ulonglong2 b01 = bp[0], b23 = bp[1];
        fma2(acc0, a, b01.x); fma2(acc1, a, b01.y);
        fma2(acc2, a, b23.x); fma2(acc3, a, b23.y);
    }

    const int r0 = m0 + 2 * ty;
    const int t0 = r0 & (TT - 1);
    const int nb = n0 + 4 * tx;
    ull accs[4] = {acc0, acc1, acc2, acc3};
    #pragma unroll
    for (int c = 0; c < 4; c++) {
        float2 v = unpack2(accs[c]);
        int n = nb + c;
        float b = bin[n];
        float u0 = v.x + b;
        float u1 = v.y + b;
        X[(size_t)r0 * NN + n]       = (t0 == 0) ? (LEAK * tanhf(u0)) : u0;
        X[(size_t)(r0 + 1) * NN + n] = u1;
    }
}

// ---------------------------------------------------------------------------
// Persistent recurrence: 128 CTAs = 8 m-slabs x 16 n-tiles, 256 threads.
// Xsd[k][RK]: dup-quad (x_m,x_m,x_m1,x_m1) for row-pair p at word
//   k*RK + (4p ^ ((k>>2 & 3) << 3)).    Ws[k][32] plain.
// GEMM per k per thread: LDS.128 (a quad) + LDS.64 (w pair) + 2 FFMA2.
// ---------------------------------------------------------------------------
__global__ __launch_bounds__(256, 1) void esn_persist(
    float* __restrict__ X, const float* __restrict__ Wres,
    const float* __restrict__ bres, float* __restrict__ xlast)
{
    extern __shared__ __align__(16) float smem[];
    float* Xsd = smem;               // [512][RK]
    float* Ws  = smem + NN * RK;     // [512][32]

    const int tid = threadIdx.x;
    const int bx  = blockIdx.x;
    const int grp = bx & 7;
    const int m0 = grp * 32;
    const int n0 = (bx >> 3) * 32;
    const int TN = TT * NN;
    unsigned* cnt = &g_cnt[grp * 32];

    // Stage W slab once (plain)
    {
        const int n = tid & 31;
        for (int k = tid >> 5; k < NN; k += 8)
            Ws[k * 32 + n] = Wres[k * NN + n0 + n];
    }

    // GEMM mapping: 8 warps = 2(row-halves) x 4(col-groups); thread: 2x2
    const int w  = tid >> 5, l = tid & 31;
    const int wm = w & 1, wn = w >> 1;       // wm: 16-row half, wn: 8-col group
    const int q  = l >> 2;                   // row pair in half: rows 2q,2q+1
    const int c  = l & 3;                    // col pair: cols 2c,2c+1
    const int prb  = 8 * wm + q;             // global row-pair index 0..15
    const int mloc = 16 * wm + 2 * q;        // local row (even)
    const int nloc = 8 * wn + 2 * c;         // local col (even)

    // 4 XOR-swizzled a-base pointers (selected by (k>>2)&3)
    const float* aB[4];
    #pragma unroll
    for (int s = 0; s < 4; s++) aB[s] = Xsd + ((4 * prb) ^ (s << 3));
    const float* wB = Ws + nloc;

    // staging mapping: p = row pair 0..15, kq = k4 phase 0..15
    const int p  = tid >> 4;
    const int kq = tid & 15;
    const int ssw = (kq & 3) << 3;           // staging swizzle (const per thread)

    const float2 br2 = *(const float2*)&bres[n0 + nloc];

    for (int t = 1; t < TT; t++) {
        // ---- prefetch epilogue U operands first (independent of barrier) ----
        const int r0 = m0 + mloc;
        size_t base = (size_t)r0 * TN + (size_t)t * NN + n0 + nloc;
        float2 u0 = __ldcg((const float2*)&X[base]);
        float2 u1 = __ldcg((const float2*)&X[base + TN]);

        // ---- stage x_prev slab (rows 2p,2p+1) as swizzled dup-quads ----
        const float4* rr0 = (const float4*)(X + (size_t)(m0 + 2 * p) * TN + (size_t)(t - 1) * NN);
        const float4* rr1 = (const float4*)(X + (size_t)(m0 + 2 * p + 1) * TN + (size_t)(t - 1) * NN);
        #pragma unroll
        for (int j = 0; j < 8; j++) {
            int k4 = kq + 16 * j;
            float4 v0 = __ldcg(rr0 + k4);
            float4 v1 = __ldcg(rr1 + k4);
            int kbase = 4 * k4;
            int woff = (4 * p) ^ ssw;
            float* d = Xsd + (size_t)kbase * RK + woff;
            *(float4*)(d + 0 * RK) = make_float4(v0.x, v0.x, v1.x, v1.x);
            *(float4*)(d + 1 * RK) = make_float4(v0.y, v0.y, v1.y, v1.y);
            *(float4*)(d + 2 * RK) = make_float4(v0.z, v0.z, v1.z, v1.z);
            *(float4*)(d + 3 * RK) = make_float4(v0.w, v0.w, v1.w, v1.w);
        }
        __syncthreads();

        // ---- GEMM: per k: LDS.128 + LDS.64 + 2 FFMA2 ----
        ull acc0 = 0, acc1 = 0;
        #pragma unroll 16
        for (int k = 0; k < NN; k++) {
            ulonglong2 a = *(const ulonglong2*)(aB[(k >> 2) & 3] + (size_t)k * RK);
            ull b = *(const ull*)(wB + k * 32);
            fma2(acc0, a.x, b);      // rows m, cols (n, n+1)
            fma2(acc1, a.y, b);      // row m+1
        }

        // ---- epilogue ----
        float2 s0 = unpack2(acc0), s1 = unpack2(acc1);
        // x_prev[m, n0+nloc(+1)] from swizzled Xsd
        int kk0 = n0 + nloc, kk1 = kk0 + 1;
        int off0 = (4 * prb) ^ (((kk0 >> 2) & 3) << 3);   // same for kk1 (kk0 even)
        const float* xr0 = Xsd + (size_t)kk0 * RK + off0;
        const float* xr1 = Xsd + (size_t)kk1 * RK + off0;
        float xp00 = xr0[0], xp10 = xr0[2];   // col kk0: rows m, m+1
        float xp01 = xr1[0], xp11 = xr1[2];   // col kk1

        float2 o0, o1;
        o0.x = 0.5f * xp00 + 0.5f * tanhf(u0.x + s0.x + br2.x);
        o0.y = 0.5f * xp01 + 0.5f * tanhf(u0.y + s0.y + br2.y);
        o1.x = 0.5f * xp10 + 0.5f * tanhf(u1.x + s1.x + br2.x);
        o1.y = 0.5f * xp11 + 0.5f * tanhf(u1.y + s1.y + br2.y);

        *(float2*)&X[base]      = o0;
        *(float2*)&X[base + TN] = o1;
        if (t == TT - 1) {
            *(float2*)&xlast[(size_t)r0 * NN + n0 + nloc]       = o0;
            *(float2*)&xlast[(size_t)(r0 + 1) * NN + n0 + nloc] = o1;
        }

        // ---- 16-CTA group barrier ----
        if (t < TT - 1) {
            __syncthreads();
            if (tid == 0) {
                atom_add_rel(cnt, 1u);
                unsigned target = (unsigned)t * GRP_SZ;
                while (ld_acq(cnt) < target) { }
            }
            __syncthreads();
        }
    }
}

extern "C" void kernel_launch(void* const* d_in, const int* in_sizes, int n_in,
                              void* d_out, int out_size)
{
    const float* inp  = (const float*)d_in[0];
    const float* Win  = (const float*)d_in[1];
    const float* bin  = (const float*)d_in[2];
    const float* Wres = (const float*)d_in[3];
    const float* bres = (const float*)d_in[4];

    float* X = (float*)d_out;                       // (B, T, N)
    float* xlast = X + (size_t)BB * TT * NN;        // (B, N)

    const int smem_bytes = (NN * RK + NN * 32) * sizeof(float);  // 204800
    cudaFuncSetAttribute(esn_persist, cudaFuncAttributeMaxDynamicSharedMemorySize, smem_bytes);

    dim3 g1(BB * TT / 32, NN / 32);
    proj_kernel<<<g1, 128>>>(inp, Win, bin, X);

    init_kernel<<<1, NGRP>>>();

    esn_persist<<<NCTA, 256, smem_bytes>>>(X, Wres, bres, xlast);
}